// round 2
// baseline (speedup 1.0000x reference)
#include <cuda_runtime.h>

#define IN_CH 128
#define HID   64
#define HEADS 4
#define MAXN  50176

static __device__ float g_h[MAXN * HID];      // projected features [N,64]
static __device__ float g_rn[MAXN * HEADS];   // per-head reciprocal norms [N,4]
static __device__ float g_acc[MAXN * HID];    // scatter-add accumulator [N,64]
static __device__ int   g_is64;               // edge_index dtype flag

// ---------------------------------------------------------------------------
// Detect whether edge_index is int64 (high 32-bit words of in-range values
// are zero) or int32.
// ---------------------------------------------------------------------------
__global__ void detect_dtype_kernel(const int* __restrict__ ei) {
    int cnt = 0;
    for (int i = 0; i < 64; i++) {
        if (ei[2 * i + 1] != 0) cnt++;
    }
    g_is64 = (cnt == 0) ? 1 : 0;
}

// ---------------------------------------------------------------------------
// Kernel 1: h = x @ lin_w^T  (N x 128 @ 128 x 64), fused per-head rnorm and
// accumulator zeroing (saves a separate 12.8 MB zero pass).
// Block: 256 threads, tile 64 nodes x 64 outputs, BK=32, 4x4 register tile.
// ---------------------------------------------------------------------------
__global__ void __launch_bounds__(256) gemm_norm_kernel(
    const float* __restrict__ x, const float* __restrict__ w, int N)
{
    __shared__ float xs[32][68];  // xs[k][m]  (m = node within tile)
    __shared__ float ws[32][68];  // ws[k][j]  (j = output channel)

    const int tid = threadIdx.x;
    const int tx = tid & 15;      // output group (4 outputs each)
    const int ty = tid >> 4;      // node group (4 nodes each)
    const int nb = blockIdx.x * 64;

    float acc[4][4];
#pragma unroll
    for (int a = 0; a < 4; a++)
#pragma unroll
        for (int b = 0; b < 4; b++) acc[a][b] = 0.f;

    for (int kc = 0; kc < IN_CH; kc += 32) {
        // Stage x tile: 64 nodes x 32 k  (512 float4, 2 per thread)
#pragma unroll
        for (int r = 0; r < 2; r++) {
            int idx = tid + 256 * r;
            int m = idx & 63, k4 = idx >> 6;
            float4 v = make_float4(0.f, 0.f, 0.f, 0.f);
            int node = nb + m;
            if (node < N)
                v = *reinterpret_cast<const float4*>(&x[node * IN_CH + kc + k4 * 4]);
            xs[k4 * 4 + 0][m] = v.x; xs[k4 * 4 + 1][m] = v.y;
            xs[k4 * 4 + 2][m] = v.z; xs[k4 * 4 + 3][m] = v.w;
        }
        // Stage w tile: 64 j x 32 k (transposed into ws[k][j])
#pragma unroll
        for (int r = 0; r < 2; r++) {
            int idx = tid + 256 * r;
            int j = idx & 63, k4 = idx >> 6;
            float4 v = *reinterpret_cast<const float4*>(&w[j * IN_CH + kc + k4 * 4]);
            ws[k4 * 4 + 0][j] = v.x; ws[k4 * 4 + 1][j] = v.y;
            ws[k4 * 4 + 2][j] = v.z; ws[k4 * 4 + 3][j] = v.w;
        }
        __syncthreads();

#pragma unroll
        for (int k = 0; k < 32; k++) {
            float4 xv = *reinterpret_cast<float4*>(&xs[k][ty * 4]);
            float4 wv = *reinterpret_cast<float4*>(&ws[k][tx * 4]);
            float xr[4] = {xv.x, xv.y, xv.z, xv.w};
            float wr[4] = {wv.x, wv.y, wv.z, wv.w};
#pragma unroll
            for (int a = 0; a < 4; a++)
#pragma unroll
                for (int b = 0; b < 4; b++) acc[a][b] += xr[a] * wr[b];
        }
        __syncthreads();
    }

    // Epilogue: write h, zero g_acc, compute per-head reciprocal norms.
    // Thread's 4 outputs (tx*4 .. tx*4+3) lie within head = tx>>2.
#pragma unroll
    for (int mi = 0; mi < 4; mi++) {
        int node = nb + ty * 4 + mi;
        float s = acc[mi][0] * acc[mi][0] + acc[mi][1] * acc[mi][1]
                + acc[mi][2] * acc[mi][2] + acc[mi][3] * acc[mi][3];
        // reduce across the 4 lanes covering one head (lane groups aligned mod 4)
        s += __shfl_xor_sync(0xffffffffu, s, 1);
        s += __shfl_xor_sync(0xffffffffu, s, 2);
        if (node < N) {
            float4 hv = make_float4(acc[mi][0], acc[mi][1], acc[mi][2], acc[mi][3]);
            *reinterpret_cast<float4*>(&g_h[node * HID + tx * 4]) = hv;
            *reinterpret_cast<float4*>(&g_acc[node * HID + tx * 4]) =
                make_float4(0.f, 0.f, 0.f, 0.f);
            if ((tx & 3) == 0) {
                g_rn[node * HEADS + (tx >> 2)] = 1.0f / fmaxf(sqrtf(s), 1e-12f);
            }
        }
    }
}

// ---------------------------------------------------------------------------
// Kernel 2: per-edge cosine-scaled message + scatter-add (vector reduction).
// 16 threads per edge; thread t owns dims [4t, 4t+4); head = t>>2.
// ---------------------------------------------------------------------------
__global__ void __launch_bounds__(256) edge_kernel(
    const long long* __restrict__ ei, int E)
{
    const int t = threadIdx.x & 15;
    const int e = (blockIdx.x * 256 + threadIdx.x) >> 4;
    if (e >= E) return;

    int row, col;
    if (g_is64) {
        row = (int)ei[e];
        col = (int)ei[E + e];
    } else {
        const int* e32 = reinterpret_cast<const int*>(ei);
        row = e32[e];
        col = e32[E + e];
    }

    const int head = t >> 2;
    float4 hc = *reinterpret_cast<const float4*>(&g_h[col * HID + t * 4]);
    float4 hr = *reinterpret_cast<const float4*>(&g_h[row * HID + t * 4]);

    float d = hc.x * hr.x + hc.y * hr.y + hc.z * hr.z + hc.w * hr.w;
    d += __shfl_xor_sync(0xffffffffu, d, 1);
    d += __shfl_xor_sync(0xffffffffu, d, 2);

    float cosv = d * g_rn[col * HEADS + head] * g_rn[row * HEADS + head];
    cosv = fminf(fmaxf(cosv, 1e-6f), 1.0f);   // clip; B_EXP=2 => scale = cos

    float mx = hc.x * cosv, my = hc.y * cosv, mz = hc.z * cosv, mw = hc.w * cosv;
    float* p = &g_acc[row * HID + t * 4];
    asm volatile("red.global.add.v4.f32 [%0], {%1,%2,%3,%4};"
                 :: "l"(p), "f"(mx), "f"(my), "f"(mz), "f"(mw) : "memory");
}

// ---------------------------------------------------------------------------
// Kernel 3: BcosLinearNoBias (64x64) + LayerNorm. One warp per node.
// bcos_w transposed in smem with pitch 65 (conflict-free).
// ---------------------------------------------------------------------------
__global__ void __launch_bounds__(256) final_kernel(
    const float* __restrict__ bw, const float* __restrict__ gamma,
    const float* __restrict__ beta, float* __restrict__ out, int N)
{
    __shared__ float swT[64 * 65];  // swT[k*65 + j] = bw[j*64 + k]
    __shared__ float wrn[64];

    const int tid = threadIdx.x;
#pragma unroll
    for (int r = 0; r < 16; r++) {
        int idx = tid + 256 * r;
        int j = idx >> 6, k = idx & 63;
        swT[k * 65 + j] = bw[idx];
    }
    __syncthreads();
    if (tid < 64) {
        float s = 0.f;
#pragma unroll
        for (int k = 0; k < 64; k++) { float v = swT[k * 65 + tid]; s += v * v; }
        wrn[tid] = 1.0f / fmaxf(sqrtf(s), 1e-12f);
    }
    __syncthreads();

    const int warp = tid >> 5, lane = tid & 31;
    const int gw = blockIdx.x * 8 + warp;
    const int nwarps = gridDim.x * 8;
    const float gm0 = gamma[lane], gm1 = gamma[lane + 32];
    const float bt0 = beta[lane],  bt1 = beta[lane + 32];

    for (int node = gw; node < N; node += nwarps) {
        float a0 = g_acc[node * HID + lane];
        float a1 = g_acc[node * HID + 32 + lane];

        float ss = a0 * a0 + a1 * a1;
#pragma unroll
        for (int o = 16; o > 0; o >>= 1) ss += __shfl_xor_sync(0xffffffffu, ss, o);
        float orn = 1.0f / fmaxf(sqrtf(ss), 1e-12f);

        float lin0 = 0.f, lin1 = 0.f;
#pragma unroll
        for (int k = 0; k < 64; k++) {
            float ak = __shfl_sync(0xffffffffu, (k < 32) ? a0 : a1, k & 31);
            lin0 += ak * swT[k * 65 + lane];
            lin1 += ak * swT[k * 65 + 32 + lane];
        }

        float c0 = fminf(fmaxf(lin0 * orn * wrn[lane],      1e-6f), 1.0f);
        float c1 = fminf(fmaxf(lin1 * orn * wrn[lane + 32], 1e-6f), 1.0f);
        float y0 = lin0 * c0;
        float y1 = lin1 * c1;

        float sum = y0 + y1;
#pragma unroll
        for (int o = 16; o > 0; o >>= 1) sum += __shfl_xor_sync(0xffffffffu, sum, o);
        float mu = sum * (1.0f / 64.0f);
        float d0 = y0 - mu, d1 = y1 - mu;
        float vs = d0 * d0 + d1 * d1;
#pragma unroll
        for (int o = 16; o > 0; o >>= 1) vs += __shfl_xor_sync(0xffffffffu, vs, o);
        float inv = rsqrtf(vs * (1.0f / 64.0f) + 1e-5f);

        out[node * HID + lane]      = d0 * inv * gm0 + bt0;
        out[node * HID + 32 + lane] = d1 * inv * gm1 + bt1;
    }
}

// ---------------------------------------------------------------------------
extern "C" void kernel_launch(void* const* d_in, const int* in_sizes, int n_in,
                              void* d_out, int out_size)
{
    const float*     x     = (const float*)d_in[0];
    const long long* ei    = (const long long*)d_in[1];
    const float*     lin_w = (const float*)d_in[2];
    const float*     bw    = (const float*)d_in[3];
    const float*     gamma = (const float*)d_in[4];
    const float*     beta  = (const float*)d_in[5];

    const int N = in_sizes[0] / IN_CH;
    const int E = in_sizes[1] / 2;

    detect_dtype_kernel<<<1, 1>>>((const int*)ei);
    gemm_norm_kernel<<<(N + 63) / 64, 256>>>(x, lin_w, N);
    edge_kernel<<<(E + 15) / 16, 256>>>(ei, E);
    final_kernel<<<448, 256>>>(bw, gamma, beta, (float*)d_out, N);
}

// round 3
// speedup vs baseline: 1.3052x; 1.3052x over previous
#include <cuda_runtime.h>

#define IN_CH 128
#define HID   64
#define HEADS 4
#define MAXN  50176

static __device__ float g_h[MAXN * HID];      // projected features [N,64]
static __device__ float g_rn[MAXN * HEADS];   // per-head reciprocal norms [N,4]
static __device__ float g_acc[MAXN * HID];    // scatter-add accumulator [N,64]
static __device__ int   g_is64;               // edge_index dtype flag

// ---------------------------------------------------------------------------
// Detect whether edge_index is int64 (high 32-bit words of in-range values
// are zero) or int32.
// ---------------------------------------------------------------------------
__global__ void detect_dtype_kernel(const int* __restrict__ ei) {
    int cnt = 0;
    for (int i = 0; i < 64; i++) {
        if (ei[2 * i + 1] != 0) cnt++;
    }
    g_is64 = (cnt == 0) ? 1 : 0;
}

// ---------------------------------------------------------------------------
// Kernel 1: h = x @ lin_w^T  (N x 128 @ 128 x 64), fused per-head rnorm and
// accumulator zeroing.
// ---------------------------------------------------------------------------
__global__ void __launch_bounds__(256) gemm_norm_kernel(
    const float* __restrict__ x, const float* __restrict__ w, int N)
{
    __shared__ float xs[32][68];  // xs[k][m]
    __shared__ float ws[32][68];  // ws[k][j]

    const int tid = threadIdx.x;
    const int tx = tid & 15;
    const int ty = tid >> 4;
    const int nb = blockIdx.x * 64;

    float acc[4][4];
#pragma unroll
    for (int a = 0; a < 4; a++)
#pragma unroll
        for (int b = 0; b < 4; b++) acc[a][b] = 0.f;

    for (int kc = 0; kc < IN_CH; kc += 32) {
#pragma unroll
        for (int r = 0; r < 2; r++) {
            int idx = tid + 256 * r;
            int m = idx & 63, k4 = idx >> 6;
            float4 v = make_float4(0.f, 0.f, 0.f, 0.f);
            int node = nb + m;
            if (node < N)
                v = *reinterpret_cast<const float4*>(&x[node * IN_CH + kc + k4 * 4]);
            xs[k4 * 4 + 0][m] = v.x; xs[k4 * 4 + 1][m] = v.y;
            xs[k4 * 4 + 2][m] = v.z; xs[k4 * 4 + 3][m] = v.w;
        }
#pragma unroll
        for (int r = 0; r < 2; r++) {
            int idx = tid + 256 * r;
            int j = idx & 63, k4 = idx >> 6;
            float4 v = *reinterpret_cast<const float4*>(&w[j * IN_CH + kc + k4 * 4]);
            ws[k4 * 4 + 0][j] = v.x; ws[k4 * 4 + 1][j] = v.y;
            ws[k4 * 4 + 2][j] = v.z; ws[k4 * 4 + 3][j] = v.w;
        }
        __syncthreads();

#pragma unroll
        for (int k = 0; k < 32; k++) {
            float4 xv = *reinterpret_cast<float4*>(&xs[k][ty * 4]);
            float4 wv = *reinterpret_cast<float4*>(&ws[k][tx * 4]);
            float xr[4] = {xv.x, xv.y, xv.z, xv.w};
            float wr[4] = {wv.x, wv.y, wv.z, wv.w};
#pragma unroll
            for (int a = 0; a < 4; a++)
#pragma unroll
                for (int b = 0; b < 4; b++) acc[a][b] += xr[a] * wr[b];
        }
        __syncthreads();
    }

#pragma unroll
    for (int mi = 0; mi < 4; mi++) {
        int node = nb + ty * 4 + mi;
        float s = acc[mi][0] * acc[mi][0] + acc[mi][1] * acc[mi][1]
                + acc[mi][2] * acc[mi][2] + acc[mi][3] * acc[mi][3];
        s += __shfl_xor_sync(0xffffffffu, s, 1);
        s += __shfl_xor_sync(0xffffffffu, s, 2);
        if (node < N) {
            float4 hv = make_float4(acc[mi][0], acc[mi][1], acc[mi][2], acc[mi][3]);
            *reinterpret_cast<float4*>(&g_h[node * HID + tx * 4]) = hv;
            *reinterpret_cast<float4*>(&g_acc[node * HID + tx * 4]) =
                make_float4(0.f, 0.f, 0.f, 0.f);
            if ((tx & 3) == 0) {
                g_rn[node * HEADS + (tx >> 2)] = 1.0f / fmaxf(sqrtf(s), 1e-12f);
            }
        }
    }
}

// ---------------------------------------------------------------------------
// Kernel 2: per-edge cosine-scaled message + scatter-add (vector reduction).
// 16 threads per edge; thread t owns dims [4t, 4t+4); head = t>>2.
// ---------------------------------------------------------------------------
__global__ void __launch_bounds__(256) edge_kernel(
    const long long* __restrict__ ei, int E)
{
    const int t = threadIdx.x & 15;
    const int e = (blockIdx.x * 256 + threadIdx.x) >> 4;
    if (e >= E) return;

    int row, col;
    if (g_is64) {
        row = (int)ei[e];
        col = (int)ei[E + e];
    } else {
        const int* e32 = reinterpret_cast<const int*>(ei);
        row = e32[e];
        col = e32[E + e];
    }

    const int head = t >> 2;
    float4 hc = *reinterpret_cast<const float4*>(&g_h[col * HID + t * 4]);
    float4 hr = *reinterpret_cast<const float4*>(&g_h[row * HID + t * 4]);

    float d = hc.x * hr.x + hc.y * hr.y + hc.z * hr.z + hc.w * hr.w;
    d += __shfl_xor_sync(0xffffffffu, d, 1);
    d += __shfl_xor_sync(0xffffffffu, d, 2);

    float cosv = d * g_rn[col * HEADS + head] * g_rn[row * HEADS + head];
    cosv = fminf(fmaxf(cosv, 1e-6f), 1.0f);   // clip; B_EXP=2 => scale = cos

    float mx = hc.x * cosv, my = hc.y * cosv, mz = hc.z * cosv, mw = hc.w * cosv;
    float* p = &g_acc[row * HID + t * 4];
    asm volatile("red.global.add.v4.f32 [%0], {%1,%2,%3,%4};"
                 :: "l"(p), "f"(mx), "f"(my), "f"(mz), "f"(mw) : "memory");
}

// ---------------------------------------------------------------------------
// Kernel 3: BcosLinearNoBias (64x64 GEMM) + LayerNorm, register-tiled.
// Block: 256 threads, 64 nodes x 64 outputs, K=64 smem-resident.
// ---------------------------------------------------------------------------
__global__ void __launch_bounds__(256) final_kernel(
    const float* __restrict__ bw, const float* __restrict__ gamma,
    const float* __restrict__ beta, float* __restrict__ out, int N)
{
    __shared__ float as[64][68];    // as[k][m]   acc tile (transposed)
    __shared__ float ws[64][68];    // ws[k][j]   bw tile (transposed)
    __shared__ float psum[4][64];   // per-quarter partial row sumsq
    __shared__ float orn_s[64];     // 1/||acc_row||
    __shared__ float wrn_s[64];     // 1/||bw_j||

    const int tid = threadIdx.x;
    const int tx = tid & 15;        // output group (4 outputs)
    const int ty = tid >> 4;        // node group (4 nodes)
    const int nb = blockIdx.x * 64;

    // Stage acc tile (64 nodes x 64 k) + per-thread sumsq partials.
    {
        const int m = tid & 63;           // node within tile
        const int q = tid >> 6;           // quarter
        const int node = nb + m;
        float ss = 0.f;
#pragma unroll
        for (int r = 0; r < 4; r++) {
            int k4 = q + 4 * r;
            float4 v = make_float4(0.f, 0.f, 0.f, 0.f);
            if (node < N)
                v = *reinterpret_cast<const float4*>(&g_acc[node * HID + k4 * 4]);
            as[k4 * 4 + 0][m] = v.x; as[k4 * 4 + 1][m] = v.y;
            as[k4 * 4 + 2][m] = v.z; as[k4 * 4 + 3][m] = v.w;
            ss += v.x * v.x + v.y * v.y + v.z * v.z + v.w * v.w;
        }
        psum[q][m] = ss;
    }
    // Stage bw tile (64 j x 64 k, transposed).
    {
        const int j = tid & 63;
        const int q = tid >> 6;
#pragma unroll
        for (int r = 0; r < 4; r++) {
            int k4 = q + 4 * r;
            float4 v = *reinterpret_cast<const float4*>(&bw[j * HID + k4 * 4]);
            ws[k4 * 4 + 0][j] = v.x; ws[k4 * 4 + 1][j] = v.y;
            ws[k4 * 4 + 2][j] = v.z; ws[k4 * 4 + 3][j] = v.w;
        }
    }
    __syncthreads();

    if (tid < 64) {
        float s = psum[0][tid] + psum[1][tid] + psum[2][tid] + psum[3][tid];
        orn_s[tid] = 1.0f / fmaxf(sqrtf(s), 1e-12f);
    } else if (tid < 128) {
        int j = tid - 64;
        float s = 0.f;
#pragma unroll
        for (int k = 0; k < 64; k++) { float v = ws[k][j]; s += v * v; }
        wrn_s[j] = 1.0f / fmaxf(sqrtf(s), 1e-12f);
    }

    float acc[4][4];
#pragma unroll
    for (int a = 0; a < 4; a++)
#pragma unroll
        for (int b = 0; b < 4; b++) acc[a][b] = 0.f;

#pragma unroll
    for (int k = 0; k < 64; k++) {
        float4 xv = *reinterpret_cast<float4*>(&as[k][ty * 4]);
        float4 wv = *reinterpret_cast<float4*>(&ws[k][tx * 4]);
        float xr[4] = {xv.x, xv.y, xv.z, xv.w};
        float wr[4] = {wv.x, wv.y, wv.z, wv.w};
#pragma unroll
        for (int a = 0; a < 4; a++)
#pragma unroll
            for (int b = 0; b < 4; b++) acc[a][b] += xr[a] * wr[b];
    }
    __syncthreads();   // orn_s/wrn_s ready (and safe: no smem rewrites)

    const float w0 = wrn_s[tx * 4 + 0], w1 = wrn_s[tx * 4 + 1];
    const float w2 = wrn_s[tx * 4 + 2], w3 = wrn_s[tx * 4 + 3];
    const float4 gm = *reinterpret_cast<const float4*>(&gamma[tx * 4]);
    const float4 bt = *reinterpret_cast<const float4*>(&beta[tx * 4]);

#pragma unroll
    for (int mi = 0; mi < 4; mi++) {
        const int node = nb + ty * 4 + mi;
        const float orn = orn_s[ty * 4 + mi];

        float l0 = acc[mi][0], l1 = acc[mi][1], l2 = acc[mi][2], l3 = acc[mi][3];
        float y0 = l0 * fminf(fmaxf(l0 * orn * w0, 1e-6f), 1.0f);
        float y1 = l1 * fminf(fmaxf(l1 * orn * w1, 1e-6f), 1.0f);
        float y2 = l2 * fminf(fmaxf(l2 * orn * w2, 1e-6f), 1.0f);
        float y3 = l3 * fminf(fmaxf(l3 * orn * w3, 1e-6f), 1.0f);

        float sum = y0 + y1 + y2 + y3;
#pragma unroll
        for (int o = 8; o > 0; o >>= 1) sum += __shfl_xor_sync(0xffffffffu, sum, o);
        float mu = sum * (1.0f / 64.0f);

        float d0 = y0 - mu, d1 = y1 - mu, d2 = y2 - mu, d3 = y3 - mu;
        float vs = d0 * d0 + d1 * d1 + d2 * d2 + d3 * d3;
#pragma unroll
        for (int o = 8; o > 0; o >>= 1) vs += __shfl_xor_sync(0xffffffffu, vs, o);
        float inv = rsqrtf(vs * (1.0f / 64.0f) + 1e-5f);

        if (node < N) {
            float4 ov = make_float4(d0 * inv * gm.x + bt.x,
                                    d1 * inv * gm.y + bt.y,
                                    d2 * inv * gm.z + bt.z,
                                    d3 * inv * gm.w + bt.w);
            *reinterpret_cast<float4*>(&out[node * HID + tx * 4]) = ov;
        }
    }
}

// ---------------------------------------------------------------------------
extern "C" void kernel_launch(void* const* d_in, const int* in_sizes, int n_in,
                              void* d_out, int out_size)
{
    const float*     x     = (const float*)d_in[0];
    const long long* ei    = (const long long*)d_in[1];
    const float*     lin_w = (const float*)d_in[2];
    const float*     bw    = (const float*)d_in[3];
    const float*     gamma = (const float*)d_in[4];
    const float*     beta  = (const float*)d_in[5];

    const int N = in_sizes[0] / IN_CH;
    const int E = in_sizes[1] / 2;

    detect_dtype_kernel<<<1, 1>>>((const int*)ei);
    gemm_norm_kernel<<<(N + 63) / 64, 256>>>(x, lin_w, N);
    edge_kernel<<<(E + 15) / 16, 256>>>(ei, E);
    final_kernel<<<(N + 63) / 64, 256>>>(bw, gamma, beta, (float*)d_out, N);
}

// round 5
// speedup vs baseline: 1.3108x; 1.0043x over previous
#include <cuda_runtime.h>
#include <cuda_fp16.h>

#define IN_CH 128
#define HID   64
#define HEADS 4
#define MAXN  50176

static __device__ uint4 g_h2[MAXN * 8];       // fp16 projected features [N,64] (128B/node)
static __device__ float g_rn[MAXN * HEADS];   // per-head reciprocal norms [N,4]
static __device__ float g_acc[MAXN * HID];    // scatter-add accumulator [N,64]
static __device__ int   g_is64;               // edge_index dtype flag

// ---------------------------------------------------------------------------
// Detect whether edge_index is int64 (high words of in-range values all zero).
// ---------------------------------------------------------------------------
__global__ void detect_dtype_kernel(const int* __restrict__ ei) {
    int cnt = 0;
    for (int i = 0; i < 64; i++) {
        if (ei[2 * i + 1] != 0) cnt++;
    }
    g_is64 = (cnt == 0) ? 1 : 0;
}

// ---------------------------------------------------------------------------
// Kernel 1: h = x @ lin_w^T  (N x 128 @ 128 x 64), fused per-head rnorm,
// fp16 h write, and accumulator zeroing.
// ---------------------------------------------------------------------------
__global__ void __launch_bounds__(256) gemm_norm_kernel(
    const float* __restrict__ x, const float* __restrict__ w, int N)
{
    __shared__ float xs[32][68];  // xs[k][m]
    __shared__ float ws[32][68];  // ws[k][j]

    const int tid = threadIdx.x;
    const int tx = tid & 15;
    const int ty = tid >> 4;
    const int nb = blockIdx.x * 64;

    float acc[4][4];
#pragma unroll
    for (int a = 0; a < 4; a++)
#pragma unroll
        for (int b = 0; b < 4; b++) acc[a][b] = 0.f;

    for (int kc = 0; kc < IN_CH; kc += 32) {
#pragma unroll
        for (int r = 0; r < 2; r++) {
            int idx = tid + 256 * r;
            int m = idx & 63, k4 = idx >> 6;
            float4 v = make_float4(0.f, 0.f, 0.f, 0.f);
            int node = nb + m;
            if (node < N)
                v = *reinterpret_cast<const float4*>(&x[node * IN_CH + kc + k4 * 4]);
            xs[k4 * 4 + 0][m] = v.x; xs[k4 * 4 + 1][m] = v.y;
            xs[k4 * 4 + 2][m] = v.z; xs[k4 * 4 + 3][m] = v.w;
        }
#pragma unroll
        for (int r = 0; r < 2; r++) {
            int idx = tid + 256 * r;
            int j = idx & 63, k4 = idx >> 6;
            float4 v = *reinterpret_cast<const float4*>(&w[j * IN_CH + kc + k4 * 4]);
            ws[k4 * 4 + 0][j] = v.x; ws[k4 * 4 + 1][j] = v.y;
            ws[k4 * 4 + 2][j] = v.z; ws[k4 * 4 + 3][j] = v.w;
        }
        __syncthreads();

#pragma unroll
        for (int k = 0; k < 32; k++) {
            float4 xv = *reinterpret_cast<float4*>(&xs[k][ty * 4]);
            float4 wv = *reinterpret_cast<float4*>(&ws[k][tx * 4]);
            float xr[4] = {xv.x, xv.y, xv.z, xv.w};
            float wr[4] = {wv.x, wv.y, wv.z, wv.w};
#pragma unroll
            for (int a = 0; a < 4; a++)
#pragma unroll
                for (int b = 0; b < 4; b++) acc[a][b] += xr[a] * wr[b];
        }
        __syncthreads();
    }

#pragma unroll
    for (int mi = 0; mi < 4; mi++) {
        int node = nb + ty * 4 + mi;
        float s = acc[mi][0] * acc[mi][0] + acc[mi][1] * acc[mi][1]
                + acc[mi][2] * acc[mi][2] + acc[mi][3] * acc[mi][3];
        s += __shfl_xor_sync(0xffffffffu, s, 1);
        s += __shfl_xor_sync(0xffffffffu, s, 2);
        if (node < N) {
            __half2* hp = reinterpret_cast<__half2*>(g_h2) + node * 32 + tx * 2;
            hp[0] = __floats2half2_rn(acc[mi][0], acc[mi][1]);
            hp[1] = __floats2half2_rn(acc[mi][2], acc[mi][3]);
            *reinterpret_cast<float4*>(&g_acc[node * HID + tx * 4]) =
                make_float4(0.f, 0.f, 0.f, 0.f);
            if ((tx & 3) == 0) {
                g_rn[node * HEADS + (tx >> 2)] = 1.0f / fmaxf(sqrtf(s), 1e-12f);
            }
        }
    }
}

// ---------------------------------------------------------------------------
// Kernel 2: per-edge cosine-scaled message + scatter-add.
// 8 threads per edge; thread t owns dims [8t, 8t+8); head = t>>1.
// fp16 feature gather (one LDG.128 per node row per thread).
// ---------------------------------------------------------------------------
__global__ void __launch_bounds__(256) edge_kernel(
    const long long* __restrict__ ei, int E)
{
    const int t = threadIdx.x & 7;
    const int e = (blockIdx.x * 256 + threadIdx.x) >> 3;
    if (e >= E) return;

    int row, col;
    if (g_is64) {
        row = (int)ei[e];
        col = (int)ei[E + e];
    } else {
        const int* e32 = reinterpret_cast<const int*>(ei);
        row = e32[e];
        col = e32[E + e];
    }

    const int head = t >> 1;
    uint4 rc = g_h2[col * 8 + t];
    uint4 rr = g_h2[row * 8 + t];

    const __half2* hc2 = reinterpret_cast<const __half2*>(&rc);
    const __half2* hr2 = reinterpret_cast<const __half2*>(&rr);

    float2 c[4], r[4];
#pragma unroll
    for (int i = 0; i < 4; i++) { c[i] = __half22float2(hc2[i]); r[i] = __half22float2(hr2[i]); }

    float d = 0.f;
#pragma unroll
    for (int i = 0; i < 4; i++) d += c[i].x * r[i].x + c[i].y * r[i].y;
    d += __shfl_xor_sync(0xffffffffu, d, 1);   // partner thread of same head

    float cosv = d * g_rn[col * HEADS + head] * g_rn[row * HEADS + head];
    cosv = fminf(fmaxf(cosv, 1e-6f), 1.0f);    // clip; B_EXP=2 => scale = cos

    float* p = &g_acc[row * HID + t * 8];
    asm volatile("red.global.add.v4.f32 [%0], {%1,%2,%3,%4};"
                 :: "l"(p),
                    "f"(c[0].x * cosv), "f"(c[0].y * cosv),
                    "f"(c[1].x * cosv), "f"(c[1].y * cosv) : "memory");
    asm volatile("red.global.add.v4.f32 [%0], {%1,%2,%3,%4};"
                 :: "l"(p + 4),
                    "f"(c[2].x * cosv), "f"(c[2].y * cosv),
                    "f"(c[3].x * cosv), "f"(c[3].y * cosv) : "memory");
}

// ---------------------------------------------------------------------------
// Kernel 3: BcosLinearNoBias (64x64 GEMM) + LayerNorm, persistent blocks:
// bw tile + wrn staged once, loop over node tiles.
// ---------------------------------------------------------------------------
__global__ void __launch_bounds__(256) final_kernel(
    const float* __restrict__ bw, const float* __restrict__ gamma,
    const float* __restrict__ beta, float* __restrict__ out, int N)
{
    __shared__ float as[64][68];    // as[k][m]   acc tile (transposed)
    __shared__ float ws[64][68];    // ws[k][j]   bw tile (transposed)
    __shared__ float psum[4][64];   // per-quarter partial row sumsq
    __shared__ float orn_s[64];     // 1/||acc_row||
    __shared__ float wrn_s[64];     // 1/||bw_j||

    const int tid = threadIdx.x;
    const int tx = tid & 15;
    const int ty = tid >> 4;

    // Stage bw once (transposed) and compute weight-row rnorms once.
    {
        const int j = tid & 63;
        const int q = tid >> 6;
#pragma unroll
        for (int rr = 0; rr < 4; rr++) {
            int k4 = q + 4 * rr;
            float4 v = *reinterpret_cast<const float4*>(&bw[j * HID + k4 * 4]);
            ws[k4 * 4 + 0][j] = v.x; ws[k4 * 4 + 1][j] = v.y;
            ws[k4 * 4 + 2][j] = v.z; ws[k4 * 4 + 3][j] = v.w;
        }
    }
    __syncthreads();
    if (tid < 64) {
        float s = 0.f;
#pragma unroll
        for (int k = 0; k < 64; k++) { float v = ws[k][tid]; s += v * v; }
        wrn_s[tid] = 1.0f / fmaxf(sqrtf(s), 1e-12f);
    }
    __syncthreads();

    const float w0 = wrn_s[tx * 4 + 0], w1 = wrn_s[tx * 4 + 1];
    const float w2 = wrn_s[tx * 4 + 2], w3 = wrn_s[tx * 4 + 3];
    const float4 gm = *reinterpret_cast<const float4*>(&gamma[tx * 4]);
    const float4 bt = *reinterpret_cast<const float4*>(&beta[tx * 4]);

    const int ntiles = (N + 63) >> 6;
    for (int tile = blockIdx.x; tile < ntiles; tile += gridDim.x) {
        const int nb = tile * 64;

        // Stage acc tile + per-thread sumsq partials.
        {
            const int m = tid & 63;
            const int q = tid >> 6;
            const int node = nb + m;
            float ss = 0.f;
#pragma unroll
            for (int rr = 0; rr < 4; rr++) {
                int k4 = q + 4 * rr;
                float4 v = make_float4(0.f, 0.f, 0.f, 0.f);
                if (node < N)
                    v = *reinterpret_cast<const float4*>(&g_acc[node * HID + k4 * 4]);
                as[k4 * 4 + 0][m] = v.x; as[k4 * 4 + 1][m] = v.y;
                as[k4 * 4 + 2][m] = v.z; as[k4 * 4 + 3][m] = v.w;
                ss += v.x * v.x + v.y * v.y + v.z * v.z + v.w * v.w;
            }
            psum[q][m] = ss;
        }
        __syncthreads();

        if (tid < 64) {
            float s = psum[0][tid] + psum[1][tid] + psum[2][tid] + psum[3][tid];
            orn_s[tid] = 1.0f / fmaxf(sqrtf(s), 1e-12f);
        }

        float acc[4][4];
#pragma unroll
        for (int a = 0; a < 4; a++)
#pragma unroll
            for (int b = 0; b < 4; b++) acc[a][b] = 0.f;

#pragma unroll
        for (int k = 0; k < 64; k++) {
            float4 xv = *reinterpret_cast<float4*>(&as[k][ty * 4]);
            float4 wv = *reinterpret_cast<float4*>(&ws[k][tx * 4]);
            float xr[4] = {xv.x, xv.y, xv.z, xv.w};
            float wr[4] = {wv.x, wv.y, wv.z, wv.w};
#pragma unroll
            for (int a = 0; a < 4; a++)
#pragma unroll
                for (int b = 0; b < 4; b++) acc[a][b] += xr[a] * wr[b];
        }
        __syncthreads();   // orn_s ready; as reads done

#pragma unroll
        for (int mi = 0; mi < 4; mi++) {
            const int node = nb + ty * 4 + mi;
            const float orn = orn_s[ty * 4 + mi];

            float l0 = acc[mi][0], l1 = acc[mi][1], l2 = acc[mi][2], l3 = acc[mi][3];
            float y0 = l0 * fminf(fmaxf(l0 * orn * w0, 1e-6f), 1.0f);
            float y1 = l1 * fminf(fmaxf(l1 * orn * w1, 1e-6f), 1.0f);
            float y2 = l2 * fminf(fmaxf(l2 * orn * w2, 1e-6f), 1.0f);
            float y3 = l3 * fminf(fmaxf(l3 * orn * w3, 1e-6f), 1.0f);

            float sum = y0 + y1 + y2 + y3;
#pragma unroll
            for (int o = 8; o > 0; o >>= 1) sum += __shfl_xor_sync(0xffffffffu, sum, o);
            float mu = sum * (1.0f / 64.0f);

            float d0 = y0 - mu, d1 = y1 - mu, d2 = y2 - mu, d3 = y3 - mu;
            float vs = d0 * d0 + d1 * d1 + d2 * d2 + d3 * d3;
#pragma unroll
            for (int o = 8; o > 0; o >>= 1) vs += __shfl_xor_sync(0xffffffffu, vs, o);
            float inv = rsqrtf(vs * (1.0f / 64.0f) + 1e-5f);

            if (node < N) {
                float4 ov = make_float4(d0 * inv * gm.x + bt.x,
                                        d1 * inv * gm.y + bt.y,
                                        d2 * inv * gm.z + bt.z,
                                        d3 * inv * gm.w + bt.w);
                *reinterpret_cast<float4*>(&out[node * HID + tx * 4]) = ov;
            }
        }
        __syncthreads();   // protect psum/orn_s before next tile staging
    }
}

// ---------------------------------------------------------------------------
extern "C" void kernel_launch(void* const* d_in, const int* in_sizes, int n_in,
                              void* d_out, int out_size)
{
    const float*     x     = (const float*)d_in[0];
    const long long* ei    = (const long long*)d_in[1];
    const float*     lin_w = (const float*)d_in[2];
    const float*     bw    = (const float*)d_in[3];
    const float*     gamma = (const float*)d_in[4];
    const float*     beta  = (const float*)d_in[5];

    const int N = in_sizes[0] / IN_CH;
    const int E = in_sizes[1] / 2;

    detect_dtype_kernel<<<1, 1>>>((const int*)ei);
    gemm_norm_kernel<<<(N + 63) / 64, 256>>>(x, lin_w, N);
    edge_kernel<<<(E + 31) / 32, 256>>>(ei, E);
    final_kernel<<<296, 256>>>(bw, gamma, beta, (float*)d_out, N);
}